// round 1
// baseline (speedup 1.0000x reference)
#include <cuda_runtime.h>

#define B_ 64
#define T_ 800
#define J_ 50
#define D_ 200

constexpr int TPB1 = 256;
constexpr int NW   = 8;     // warps per block
constexpr int TT   = 4;     // t-rows per warp
constexpr int TBLK = NW * TT;   // 32 t-rows per block
constexpr int JPAD = 64;        // padded J (zero rows -> no predication in s-phase)
constexpr int UPITCH  = 212;    // floats per u row in smem (53 float4, odd -> conflict-free)
constexpr int UPITCH4 = 53;
constexpr int D4 = D_ / 4;      // 50

// scratch (no cudaMalloc allowed)
__device__ float g_m[B_ * T_];
__device__ __align__(16) float g_q2c[B_ * D_];

// ---- packed f32x2 helpers (FFMA2: 2 MACs / instruction) ----
__device__ __forceinline__ void fma2(unsigned long long& d, unsigned long long a, unsigned long long b) {
    asm("fma.rn.f32x2 %0, %1, %2, %0;" : "+l"(d) : "l"(a), "l"(b));
}
__device__ __forceinline__ float2 unpack2(unsigned long long v) {
    float2 r; asm("mov.b64 {%0, %1}, %2;" : "=f"(r.x), "=f"(r.y) : "l"(v)); return r;
}
__device__ __forceinline__ float warpSum(float v) {
    #pragma unroll
    for (int o = 16; o > 0; o >>= 1) v += __shfl_xor_sync(0xffffffffu, v, o);
    return v;
}
__device__ __forceinline__ float warpMax(float v) {
    #pragma unroll
    for (int o = 16; o > 0; o >>= 1) v = fmaxf(v, __shfl_xor_sync(0xffffffffu, v, o));
    return v;
}

// =====================================================================
// K1: per (b, t): s row, softmax over J, c2q, write out[:, 0:600], emit m[b,t]
// =====================================================================
__global__ __launch_bounds__(TPB1) void bidaf_k1(
    const float* __restrict__ h, const float* __restrict__ u,
    const float* __restrict__ w_h, const float* __restrict__ b_h,
    const float* __restrict__ w_u, const float* __restrict__ b_u,
    const float* __restrict__ w_hu, const float* __restrict__ b_hu,
    float* __restrict__ out)
{
    extern __shared__ char smem_raw[];
    float*  u_s  = (float*)smem_raw;                    // JPAD * UPITCH
    float*  hw_s = u_s + JPAD * UPITCH;                 // NW * TT * D_
    float2* a2_s = (float2*)(hw_s + NW * TT * D_);      // NW * TT * JPAD (duplicated pairs)
    float*  su_s = (float*)(a2_s + NW * TT * JPAD);     // JPAD

    const int b   = blockIdx.y;
    const int t0  = blockIdx.x * TBLK;
    const int tid = threadIdx.x;
    const int warp = tid >> 5, lane = tid & 31;

    const float4* u4g = (const float4*)u;
    const float4* h4g = (const float4*)h;
    float4* us4 = (float4*)u_s;

    // ---- load u[b] tile into smem (zero the pad rows) ----
    for (int idx = tid; idx < JPAD * UPITCH4; idx += TPB1) {
        int j = idx / UPITCH4, k = idx - j * UPITCH4;
        float4 v = make_float4(0.f, 0.f, 0.f, 0.f);
        if (j < J_ && k < D4) v = u4g[(b * J_ + j) * D4 + k];
        us4[j * UPITCH4 + k] = v;
    }
    const float bias = b_h[0] + b_u[0] + b_hu[0];
    __syncthreads();

    // ---- su_s[j] = dot(u_j, w_u) + bias ; pad rows -> -1e30 ----
    const float4* wu4 = (const float4*)w_u;
    for (int j = warp; j < JPAD; j += NW) {
        if (j < J_) {
            float acc = 0.f;
            for (int k = lane; k < D4; k += 32) {
                float4 a = us4[j * UPITCH4 + k], w = wu4[k];
                acc += a.x * w.x + a.y * w.y + a.z * w.z + a.w * w.w;
            }
            acc = warpSum(acc);
            if (lane == 0) su_s[j] = acc + bias;
        } else if (lane == 0) su_s[j] = -1e30f;
    }
    __syncthreads();

    // ---- phase A: per-warp h rows premultiplied by w_hu, plus sh = dot(h, w_h) ----
    const float4* whu4 = (const float4*)w_hu;
    const float4* wh4  = (const float4*)w_h;
    float4* hw4 = (float4*)hw_s;
    const int tw = t0 + warp * TT;
    float sh[TT];
    #pragma unroll
    for (int tt = 0; tt < TT; tt++) {
        int t = tw + tt;
        long rb = (long)(b * T_ + t) * D4;
        float4 a = h4g[rb + lane];
        float4 w1 = whu4[lane];
        hw4[warp * (TT * D4) + tt * D4 + lane] =
            make_float4(a.x * w1.x, a.y * w1.y, a.z * w1.z, a.w * w1.w);
        float4 w2 = wh4[lane];
        float p = a.x * w2.x + a.y * w2.y + a.z * w2.z + a.w * w2.w;
        if (lane < D4 - 32) {   // lanes 0..17 cover float4 idx 32..49
            float4 a2 = h4g[rb + 32 + lane];
            float4 w1b = whu4[32 + lane];
            hw4[warp * (TT * D4) + tt * D4 + 32 + lane] =
                make_float4(a2.x * w1b.x, a2.y * w1b.y, a2.z * w1b.z, a2.w * w1b.w);
            float4 w2b = wh4[32 + lane];
            p += a2.x * w2b.x + a2.y * w2b.y + a2.z * w2b.z + a2.w * w2b.w;
        }
        sh[tt] = warpSum(p);
    }
    __syncwarp();

    // ---- phase B: s[t, j] = sum_d hw[d] * u[j, d] ; lane-per-j, FFMA2 over d-pairs ----
    unsigned long long acc[TT][2];
    #pragma unroll
    for (int tt = 0; tt < TT; tt++) { acc[tt][0] = 0ull; acc[tt][1] = 0ull; }

    const ulonglong2* usU = (const ulonglong2*)u_s;
    const ulonglong2* hwU = (const ulonglong2*)hw_s;
    const int j0 = lane, j1 = lane + 32;

    #pragma unroll 2
    for (int k = 0; k < D4; k++) {
        ulonglong2 U0 = usU[j0 * UPITCH4 + k];
        ulonglong2 U1 = usU[j1 * UPITCH4 + k];   // pad rows are zero
        #pragma unroll
        for (int tt = 0; tt < TT; tt++) {
            ulonglong2 Hb = hwU[warp * (TT * D4) + tt * D4 + k];  // broadcast
            fma2(acc[tt][0], U0.x, Hb.x);
            fma2(acc[tt][0], U0.y, Hb.y);
            fma2(acc[tt][1], U1.x, Hb.x);
            fma2(acc[tt][1], U1.y, Hb.y);
        }
    }

    // ---- softmax over j (J padded to 64; pad slots underflow to 0) ----
    const float su0 = su_s[j0], su1 = su_s[j1];
    #pragma unroll
    for (int tt = 0; tt < TT; tt++) {
        float2 p0 = unpack2(acc[tt][0]);
        float2 p1 = unpack2(acc[tt][1]);
        float s0 = p0.x + p0.y + sh[tt] + su0;
        float s1 = p1.x + p1.y + sh[tt] + su1;
        float mx = warpMax(fmaxf(s0, s1));
        float e0 = __expf(s0 - mx);
        float e1 = __expf(s1 - mx);
        float sm = warpSum(e0 + e1);
        float inv = 1.f / sm;
        float a0 = e0 * inv, a1 = e1 * inv;
        a2_s[(warp * TT + tt) * JPAD + j0] = make_float2(a0, a0);
        a2_s[(warp * TT + tt) * JPAD + j1] = make_float2(a1, a1);
        if (lane == 0) g_m[b * T_ + (tw + tt)] = mx;
    }
    __syncwarp();

    // ---- c2q[t, d] = sum_j a[t,j] * u[j,d] ; lane-per-d4-chunk, FFMA2 ----
    unsigned long long cacc[TT][2][2];
    #pragma unroll
    for (int tt = 0; tt < TT; tt++)
        #pragma unroll
        for (int c = 0; c < 2; c++) { cacc[tt][c][0] = 0ull; cacc[tt][c][1] = 0ull; }

    const bool v1 = (lane < D4 - 32);
    const int k0 = lane, k1 = 32 + lane;
    for (int j = 0; j < J_; j++) {
        ulonglong2 Ua = usU[j * UPITCH4 + k0];
        ulonglong2 Ub; Ub.x = 0ull; Ub.y = 0ull;
        if (v1) Ub = usU[j * UPITCH4 + k1];
        #pragma unroll
        for (int tt = 0; tt < TT; tt++) {
            unsigned long long aj =
                *(const unsigned long long*)&a2_s[(warp * TT + tt) * JPAD + j]; // broadcast
            fma2(cacc[tt][0][0], aj, Ua.x);
            fma2(cacc[tt][0][1], aj, Ua.y);
            fma2(cacc[tt][1][0], aj, Ub.x);
            fma2(cacc[tt][1][1], aj, Ub.y);
        }
    }

    // ---- epilogue: out[b,t, 0:200]=h, [200:400]=c2q, [400:600]=h*c2q ----
    #pragma unroll
    for (int tt = 0; tt < TT; tt++) {
        int t = tw + tt;
        long rb = (long)(b * T_ + t) * D4;
        float4* o4 = (float4*)out + (long)(b * T_ + t) * (4 * D4);
        float4 ha = h4g[rb + lane];
        float2 ca = unpack2(cacc[tt][0][0]);
        float2 cb = unpack2(cacc[tt][0][1]);
        float4 c0 = make_float4(ca.x, ca.y, cb.x, cb.y);
        o4[lane]        = ha;
        o4[50 + lane]   = c0;
        o4[100 + lane]  = make_float4(ha.x * c0.x, ha.y * c0.y, ha.z * c0.z, ha.w * c0.w);
        if (v1) {
            float4 hb2 = h4g[rb + k1];
            float2 cc = unpack2(cacc[tt][1][0]);
            float2 cd = unpack2(cacc[tt][1][1]);
            float4 c1 = make_float4(cc.x, cc.y, cd.x, cd.y);
            o4[k1]        = hb2;
            o4[50 + k1]   = c1;
            o4[100 + k1]  = make_float4(hb2.x * c1.x, hb2.y * c1.y, hb2.z * c1.z, hb2.w * c1.w);
        }
    }
}

// =====================================================================
// K2: per b: softmax over T of m[b,:], q2c[b,d] = sum_t w_t * h[b,t,d]
// =====================================================================
__global__ __launch_bounds__(256) void bidaf_k2(const float* __restrict__ h)
{
    __shared__ float ws[T_];
    __shared__ float red[8];
    const int b = blockIdx.x, tid = threadIdx.x;
    const int warp = tid >> 5, lane = tid & 31;

    float mx = -3.0e38f;
    for (int i = tid; i < T_; i += 256) mx = fmaxf(mx, g_m[b * T_ + i]);
    mx = warpMax(mx);
    if (lane == 0) red[warp] = mx;
    __syncthreads();
    float M = red[0];
    #pragma unroll
    for (int i = 1; i < 8; i++) M = fmaxf(M, red[i]);
    __syncthreads();

    float se = 0.f;
    for (int i = tid; i < T_; i += 256) {
        float e = __expf(g_m[b * T_ + i] - M);
        ws[i] = e;
        se += e;
    }
    se = warpSum(se);
    if (lane == 0) red[warp] = se;
    __syncthreads();
    float S = 0.f;
    #pragma unroll
    for (int i = 0; i < 8; i++) S += red[i];
    const float inv = 1.f / S;

    if (tid < D_) {
        const float* hp = h + (long)b * T_ * D_ + tid;
        float acc = 0.f;
        #pragma unroll 4
        for (int t = 0; t < T_; t++) acc += ws[t] * hp[(long)t * D_];
        g_q2c[b * D_ + tid] = acc * inv;
    }
}

// =====================================================================
// K3: out[b,t, 600:800] = h[b,t,:] * q2c[b,:]
// =====================================================================
__global__ __launch_bounds__(256) void bidaf_k3(const float* __restrict__ h,
                                                float* __restrict__ out)
{
    int idx = blockIdx.x * blockDim.x + threadIdx.x;  // float4 index into h
    if (idx >= B_ * T_ * D4) return;
    int d4 = idx % D4;
    int bt = idx / D4;
    int b  = bt / T_;
    float4 hv = ((const float4*)h)[idx];
    float4 q  = ((const float4*)g_q2c)[b * D4 + d4];
    ((float4*)out)[(long)bt * (4 * D4) + 150 + d4] =
        make_float4(hv.x * q.x, hv.y * q.y, hv.z * q.z, hv.w * q.w);
}

// =====================================================================
extern "C" void kernel_launch(void* const* d_in, const int* in_sizes, int n_in,
                              void* d_out, int out_size)
{
    const float* h    = (const float*)d_in[0];
    const float* u    = (const float*)d_in[1];
    const float* w_h  = (const float*)d_in[2];
    const float* b_h  = (const float*)d_in[3];
    const float* w_u  = (const float*)d_in[4];
    const float* b_u  = (const float*)d_in[5];
    const float* w_hu = (const float*)d_in[6];
    const float* b_hu = (const float*)d_in[7];
    float* out = (float*)d_out;

    constexpr int SMEM1 = (JPAD * UPITCH + NW * TT * D_) * 4  // u_s + hw_s
                        + NW * TT * JPAD * 8                  // a2_s
                        + JPAD * 4;                           // su_s
    cudaFuncSetAttribute(bidaf_k1, cudaFuncAttributeMaxDynamicSharedMemorySize, SMEM1);

    bidaf_k1<<<dim3(T_ / TBLK, B_), TPB1, SMEM1>>>(h, u, w_h, b_h, w_u, b_u, w_hu, b_hu, out);
    bidaf_k2<<<B_, 256>>>(h);
    bidaf_k3<<<(B_ * T_ * D4 + 255) / 256, 256>>>(h, out);
}

// round 2
// speedup vs baseline: 1.7576x; 1.7576x over previous
#include <cuda_runtime.h>

#define B_ 64
#define T_ 800
#define J_ 50
#define D_ 200

constexpr int TPB1 = 256;
constexpr int NW   = 8;      // warps per block
constexpr int TT   = 4;      // t-rows per warp
constexpr int TBLK = NW * TT;    // 32 t-rows per block
constexpr int UPITCH4 = 51;      // float4 per u row (51*4=204 words; 204%32=12 -> conflict-free)
constexpr int D4 = D_ / 4;       // 50
constexpr int NCHUNK = 25;       // T chunks for q2c partial reduction (800/32)

// scratch (no cudaMalloc allowed)
__device__ float  g_m[B_ * T_];
__device__ float2 g_MS[B_];                        // (max, sum) per batch
__device__ float  g_part[B_ * NCHUNK * D_];        // q2c partials
__device__ __align__(16) float g_q2c[B_ * D_];

// ---- packed f32x2 helpers ----
__device__ __forceinline__ void fma2(unsigned long long& d, unsigned long long a, unsigned long long b) {
    asm("fma.rn.f32x2 %0, %1, %2, %0;" : "+l"(d) : "l"(a), "l"(b));
}
__device__ __forceinline__ float2 unpack2(unsigned long long v) {
    float2 r; asm("mov.b64 {%0, %1}, %2;" : "=f"(r.x), "=f"(r.y) : "l"(v)); return r;
}
__device__ __forceinline__ float warpSum(float v) {
    #pragma unroll
    for (int o = 16; o > 0; o >>= 1) v += __shfl_xor_sync(0xffffffffu, v, o);
    return v;
}
__device__ __forceinline__ float warpMax(float v) {
    #pragma unroll
    for (int o = 16; o > 0; o >>= 1) v = fmaxf(v, __shfl_xor_sync(0xffffffffu, v, o));
    return v;
}

// =====================================================================
// K1: per (b, t): s row, softmax over J, c2q, write out[:, 0:600], emit m[b,t]
// smem: u_s (50*204*4 = 40800B) + hw_s (8*4*200*4 = 25600B) + su_s (200B) = 66.6KB
// 'a' (softmax weights) overlays the owning warp's hw region after phase B.
// =====================================================================
__global__ __launch_bounds__(TPB1, 3) void bidaf_k1(
    const float* __restrict__ h, const float* __restrict__ u,
    const float* __restrict__ w_h, const float* __restrict__ b_h,
    const float* __restrict__ w_u, const float* __restrict__ b_u,
    const float* __restrict__ w_hu, const float* __restrict__ b_hu,
    float* __restrict__ out)
{
    extern __shared__ char smem_raw[];
    float* u_s  = (float*)smem_raw;                  // J_ * UPITCH4*4 floats
    float* hw_s = u_s + J_ * UPITCH4 * 4;            // NW * TT * D_
    float* su_s = hw_s + NW * TT * D_;               // J_

    const int b   = blockIdx.y;
    const int t0  = blockIdx.x * TBLK;
    const int tid = threadIdx.x;
    const int warp = tid >> 5, lane = tid & 31;

    const float4* u4g = (const float4*)u;
    const float4* h4g = (const float4*)h;
    float4* us4 = (float4*)u_s;

    // ---- load u[b] tile into smem (pad column never read, skip) ----
    for (int idx = tid; idx < J_ * UPITCH4; idx += TPB1) {
        int j = idx / UPITCH4, k = idx - j * UPITCH4;
        if (k < D4) us4[j * UPITCH4 + k] = u4g[(b * J_ + j) * D4 + k];
    }
    const float bias = b_h[0] + b_u[0] + b_hu[0];
    __syncthreads();

    // ---- su_s[j] = dot(u_j, w_u) + bias ----
    const float4* wu4 = (const float4*)w_u;
    for (int j = warp; j < J_; j += NW) {
        float acc = 0.f;
        for (int k = lane; k < D4; k += 32) {
            float4 a = us4[j * UPITCH4 + k], w = wu4[k];
            acc += a.x * w.x + a.y * w.y + a.z * w.z + a.w * w.w;
        }
        acc = warpSum(acc);
        if (lane == 0) su_s[j] = acc + bias;
    }
    __syncthreads();

    // ---- phase A: hw = h * w_hu (to smem), sh = dot(h, w_h) ----
    const float4* whu4 = (const float4*)w_hu;
    const float4* wh4  = (const float4*)w_h;
    float4* hw4 = (float4*)hw_s;
    const int tw = t0 + warp * TT;
    float sh[TT];
    #pragma unroll
    for (int tt = 0; tt < TT; tt++) {
        int t = tw + tt;
        long rb = (long)(b * T_ + t) * D4;
        float4 a = h4g[rb + lane];
        float4 w1 = whu4[lane];
        hw4[warp * (TT * D4) + tt * D4 + lane] =
            make_float4(a.x * w1.x, a.y * w1.y, a.z * w1.z, a.w * w1.w);
        float4 w2 = wh4[lane];
        float p = a.x * w2.x + a.y * w2.y + a.z * w2.z + a.w * w2.w;
        if (lane < D4 - 32) {
            float4 a2 = h4g[rb + 32 + lane];
            float4 w1b = whu4[32 + lane];
            hw4[warp * (TT * D4) + tt * D4 + 32 + lane] =
                make_float4(a2.x * w1b.x, a2.y * w1b.y, a2.z * w1b.z, a2.w * w1b.w);
            float4 w2b = wh4[32 + lane];
            p += a2.x * w2b.x + a2.y * w2b.y + a2.z * w2b.z + a2.w * w2b.w;
        }
        sh[tt] = warpSum(p);
    }
    __syncwarp();

    // ---- phase B: s[t, j] = sum_d hw[d] * u[j, d] ; lane-per-j (j0=lane, j1=lane+32) ----
    const bool jv = (lane < J_ - 32);   // lane < 18: second j-slot valid
    unsigned long long acc[TT][2];
    #pragma unroll
    for (int tt = 0; tt < TT; tt++) { acc[tt][0] = 0ull; acc[tt][1] = 0ull; }

    const ulonglong2* usU = (const ulonglong2*)u_s;
    const ulonglong2* hwU = (const ulonglong2*)hw_s;
    const int j0 = lane, j1 = lane + 32;

    #pragma unroll 2
    for (int k = 0; k < D4; k++) {
        ulonglong2 U0 = usU[j0 * UPITCH4 + k];
        ulonglong2 U1; U1.x = 0ull; U1.y = 0ull;
        if (jv) U1 = usU[j1 * UPITCH4 + k];
        #pragma unroll
        for (int tt = 0; tt < TT; tt++) {
            ulonglong2 Hb = hwU[warp * (TT * D4) + tt * D4 + k];  // broadcast
            fma2(acc[tt][0], U0.x, Hb.x);
            fma2(acc[tt][0], U0.y, Hb.y);
            fma2(acc[tt][1], U1.x, Hb.x);
            fma2(acc[tt][1], U1.y, Hb.y);
        }
    }

    // ---- softmax over j; store a (duplicated pairs) overlaying own hw region ----
    float2* a2w = (float2*)(hw_s + warp * (TT * D_));   // warp-private overlay
    const float su0 = su_s[j0];
    const float su1 = jv ? su_s[j1] : -1e30f;
    #pragma unroll
    for (int tt = 0; tt < TT; tt++) {
        float2 p0 = unpack2(acc[tt][0]);
        float2 p1 = unpack2(acc[tt][1]);
        float s0 = p0.x + p0.y + sh[tt] + su0;
        float s1 = p1.x + p1.y + sh[tt] + su1;
        float mx = warpMax(fmaxf(s0, s1));
        float e0 = __expf(s0 - mx);
        float e1 = __expf(s1 - mx);
        float sm = warpSum(e0 + e1);
        float inv = 1.f / sm;
        float a0 = e0 * inv, a1 = e1 * inv;
        a2w[tt * 52 + j0] = make_float2(a0, a0);
        if (jv) a2w[tt * 52 + j1] = make_float2(a1, a1);
        if (lane == 0) g_m[b * T_ + (tw + tt)] = mx;
    }
    __syncwarp();

    // ---- c2q[t, d] = sum_j a[t,j] * u[j,d] ; lane-per-d4-chunk ----
    unsigned long long cacc[TT][2][2];
    #pragma unroll
    for (int tt = 0; tt < TT; tt++)
        #pragma unroll
        for (int c = 0; c < 2; c++) { cacc[tt][c][0] = 0ull; cacc[tt][c][1] = 0ull; }

    const bool v1 = (lane < D4 - 32);
    const int k0 = lane, k1 = 32 + lane;
    for (int j = 0; j < J_; j++) {
        ulonglong2 Ua = usU[j * UPITCH4 + k0];
        ulonglong2 Ub; Ub.x = 0ull; Ub.y = 0ull;
        if (v1) Ub = usU[j * UPITCH4 + k1];
        #pragma unroll
        for (int tt = 0; tt < TT; tt++) {
            unsigned long long aj = *(const unsigned long long*)&a2w[tt * 52 + j]; // broadcast
            fma2(cacc[tt][0][0], aj, Ua.x);
            fma2(cacc[tt][0][1], aj, Ua.y);
            fma2(cacc[tt][1][0], aj, Ub.x);
            fma2(cacc[tt][1][1], aj, Ub.y);
        }
    }

    // ---- epilogue: out[b,t, 0:200]=h, [200:400]=c2q, [400:600]=h*c2q ----
    #pragma unroll
    for (int tt = 0; tt < TT; tt++) {
        int t = tw + tt;
        long rb = (long)(b * T_ + t) * D4;
        float4* o4 = (float4*)out + (long)(b * T_ + t) * (4 * D4);
        float4 ha = h4g[rb + lane];
        float2 ca = unpack2(cacc[tt][0][0]);
        float2 cb = unpack2(cacc[tt][0][1]);
        float4 c0 = make_float4(ca.x, ca.y, cb.x, cb.y);
        o4[lane]        = ha;
        o4[50 + lane]   = c0;
        o4[100 + lane]  = make_float4(ha.x * c0.x, ha.y * c0.y, ha.z * c0.z, ha.w * c0.w);
        if (v1) {
            float4 hb2 = h4g[rb + k1];
            float2 cc = unpack2(cacc[tt][1][0]);
            float2 cd = unpack2(cacc[tt][1][1]);
            float4 c1 = make_float4(cc.x, cc.y, cd.x, cd.y);
            o4[k1]        = hb2;
            o4[50 + k1]   = c1;
            o4[100 + k1]  = make_float4(hb2.x * c1.x, hb2.y * c1.y, hb2.z * c1.z, hb2.w * c1.w);
        }
    }
}

// =====================================================================
// K2m: per b, compute M = max_t m[b,t], S = sum_t exp(m-M)
// =====================================================================
__global__ __launch_bounds__(256) void bidaf_k2m()
{
    __shared__ float red[8];
    const int b = blockIdx.x, tid = threadIdx.x;
    const int warp = tid >> 5, lane = tid & 31;

    float mx = -3.0e38f;
    for (int i = tid; i < T_; i += 256) mx = fmaxf(mx, g_m[b * T_ + i]);
    mx = warpMax(mx);
    if (lane == 0) red[warp] = mx;
    __syncthreads();
    float M = red[0];
    #pragma unroll
    for (int i = 1; i < 8; i++) M = fmaxf(M, red[i]);
    __syncthreads();

    float se = 0.f;
    for (int i = tid; i < T_; i += 256) se += __expf(g_m[b * T_ + i] - M);
    se = warpSum(se);
    if (lane == 0) red[warp] = se;
    __syncthreads();
    if (tid == 0) {
        float S = 0.f;
        #pragma unroll
        for (int i = 0; i < 8; i++) S += red[i];
        g_MS[b] = make_float2(M, S);
    }
}

// =====================================================================
// K2b: partial q2c: block (chunk c, batch b) sums 32 t's weighted by exp(m-M)
// =====================================================================
__global__ __launch_bounds__(256) void bidaf_k2b(const float* __restrict__ h)
{
    __shared__ float ws[32];
    const int c = blockIdx.x, b = blockIdx.y, tid = threadIdx.x;
    const float M = g_MS[b].x;
    if (tid < 32) ws[tid] = __expf(g_m[b * T_ + c * 32 + tid] - M);
    __syncthreads();
    if (tid < D_) {
        const float* hp = h + ((long)b * T_ + c * 32) * D_ + tid;
        float acc = 0.f;
        #pragma unroll
        for (int t = 0; t < 32; t++) acc += ws[t] * hp[t * D_];
        g_part[(b * NCHUNK + c) * D_ + tid] = acc;
    }
}

// =====================================================================
// K2c: combine partials, divide by S
// =====================================================================
__global__ __launch_bounds__(256) void bidaf_k2c()
{
    const int b = blockIdx.x, tid = threadIdx.x;
    if (tid < D_) {
        float acc = 0.f;
        #pragma unroll
        for (int c = 0; c < NCHUNK; c++) acc += g_part[(b * NCHUNK + c) * D_ + tid];
        g_q2c[b * D_ + tid] = acc / g_MS[b].y;
    }
}

// =====================================================================
// K3: out[b,t, 600:800] = h[b,t,:] * q2c[b,:]
// =====================================================================
__global__ __launch_bounds__(256) void bidaf_k3(const float* __restrict__ h,
                                                float* __restrict__ out)
{
    int idx = blockIdx.x * blockDim.x + threadIdx.x;  // float4 index into h
    if (idx >= B_ * T_ * D4) return;
    int d4 = idx % D4;
    int bt = idx / D4;
    int b  = bt / T_;
    float4 hv = ((const float4*)h)[idx];
    float4 q  = ((const float4*)g_q2c)[b * D4 + d4];
    ((float4*)out)[(long)bt * (4 * D4) + 150 + d4] =
        make_float4(hv.x * q.x, hv.y * q.y, hv.z * q.z, hv.w * q.w);
}

// =====================================================================
extern "C" void kernel_launch(void* const* d_in, const int* in_sizes, int n_in,
                              void* d_out, int out_size)
{
    const float* h    = (const float*)d_in[0];
    const float* u    = (const float*)d_in[1];
    const float* w_h  = (const float*)d_in[2];
    const float* b_h  = (const float*)d_in[3];
    const float* w_u  = (const float*)d_in[4];
    const float* b_u  = (const float*)d_in[5];
    const float* w_hu = (const float*)d_in[6];
    const float* b_hu = (const float*)d_in[7];
    float* out = (float*)d_out;

    constexpr int SMEM1 = (J_ * UPITCH4 * 4 + NW * TT * D_ + J_) * 4;  // 66600 B
    cudaFuncSetAttribute(bidaf_k1, cudaFuncAttributeMaxDynamicSharedMemorySize, SMEM1);

    bidaf_k1<<<dim3(T_ / TBLK, B_), TPB1, SMEM1>>>(h, u, w_h, b_h, w_u, b_u, w_hu, b_hu, out);
    bidaf_k2m<<<B_, 256>>>();
    bidaf_k2b<<<dim3(NCHUNK, B_), 256>>>(h);
    bidaf_k2c<<<B_, 256>>>();
    bidaf_k3<<<(B_ * T_ * D4 + 255) / 256, 256>>>(h, out);
}